// round 3
// baseline (speedup 1.0000x reference)
#include <cuda_runtime.h>
#include <cstdint>

// Problem constants
#define Bk 32
#define Sk 4096
#define Ik 64
#define Rk 1024
#define Ok 8

// Main recurrence kernel partitioning
#define NB 128        // persistent blocks (<= 148 SMs -> all co-resident)
#define PB 4          // batch partitions
#define PJ 32         // j partitions
#define BPB 8         // batches per block (Bk/PB)
#define JPB 32        // j per block (Rk/PJ)

#define WT_PITCH 33   // padded pitch for W slice (conflict-free LDS)
#define RT_PITCH 12   // padded pitch for transposed r (48B rows, 16B-aligned)
#define RED_PITCH 33

#define SMEM_FLOATS (Rk*WT_PITCH + Rk*RT_PITCH + 64*RED_PITCH)
#define SMEM_BYTES  (SMEM_FLOATS*4)

// Scratch (allowed: __device__ globals). 512 MB each.
__device__ float g_pre[(size_t)Bk*Sk*Rk];
__device__ float g_rs [(size_t)Bk*Sk*Rk];
__device__ unsigned g_bar;

__global__ void reset_kernel() { g_bar = 0u; }

// ---------------------------------------------------------------------------
// Phase 1: pre[b,s,j] = sum_i x[b,s,i] * W_in[j,i]
// One block per 32-row tile (4096 blocks). FMA-bound, ~0.5 ms.
// ---------------------------------------------------------------------------
__global__ void __launch_bounds__(256) pre_kernel(const float* __restrict__ x,
                                                  const float* __restrict__ Win)
{
    __shared__ float xs[32*68];
    size_t rowBase = (size_t)blockIdx.x * 32;

    for (int idx = threadIdx.x; idx < 32*Ik; idx += 256) {
        int r = idx >> 6, i = idx & 63;
        xs[r*68 + i] = x[(rowBase + r)*Ik + i];
    }
    __syncthreads();

#pragma unroll 1
    for (int jj = 0; jj < 4; jj++) {
        int j = jj*256 + threadIdx.x;
        float4 w[16];
        const float4* wp = reinterpret_cast<const float4*>(Win + (size_t)j*Ik);
#pragma unroll
        for (int q = 0; q < 16; q++) w[q] = wp[q];

#pragma unroll 1
        for (int r = 0; r < 32; r++) {
            const float* xr = &xs[r*68];
            float a0 = 0.f, a1 = 0.f, a2 = 0.f, a3 = 0.f;
#pragma unroll
            for (int q = 0; q < 16; q += 4) {
                float4 x0 = *reinterpret_cast<const float4*>(xr + q*4);
                float4 x1 = *reinterpret_cast<const float4*>(xr + q*4 + 4);
                float4 x2 = *reinterpret_cast<const float4*>(xr + q*4 + 8);
                float4 x3 = *reinterpret_cast<const float4*>(xr + q*4 + 12);
                a0 = fmaf(w[q  ].x, x0.x, a0); a0 = fmaf(w[q  ].y, x0.y, a0);
                a0 = fmaf(w[q  ].z, x0.z, a0); a0 = fmaf(w[q  ].w, x0.w, a0);
                a1 = fmaf(w[q+1].x, x1.x, a1); a1 = fmaf(w[q+1].y, x1.y, a1);
                a1 = fmaf(w[q+1].z, x1.z, a1); a1 = fmaf(w[q+1].w, x1.w, a1);
                a2 = fmaf(w[q+2].x, x2.x, a2); a2 = fmaf(w[q+2].y, x2.y, a2);
                a2 = fmaf(w[q+2].z, x2.z, a2); a2 = fmaf(w[q+2].w, x2.w, a2);
                a3 = fmaf(w[q+3].x, x3.x, a3); a3 = fmaf(w[q+3].y, x3.y, a3);
                a3 = fmaf(w[q+3].z, x3.z, a3); a3 = fmaf(w[q+3].w, x3.w, a3);
            }
            g_pre[(rowBase + r)*Rk + j] = (a0 + a1) + (a2 + a3);
        }
    }
}

// ---------------------------------------------------------------------------
// Phase 2: persistent recurrence kernel.
// Block (pb,pj) owns batches [pb*8, pb*8+8) x columns [pj*32, pj*32+32).
// W_res slice lives transposed in SMEM for the whole kernel.
// Warp kc owns K-chunk [kc*128, kc*128+128): loads its own rT chunk and
// accumulates with packed fma.rn.f32x2 (2 fp32 FMA/instr).
// One grid-wide spin barrier per timestep (monotonic counter, reset kernel
// zeroes it before each launch so graph replays are clean).
// ---------------------------------------------------------------------------
__global__ void __launch_bounds__(256, 1) esn_main(const float* __restrict__ Wres)
{
    extern __shared__ float sm[];
    float* Wt  = sm;                    // [Rk][WT_PITCH] : Wt[k][jl] = Wres[j0+jl][k]
    float* rT  = Wt + Rk*WT_PITCH;      // [Rk][RT_PITCH] : rT[k][bl]
    float* red = rT + Rk*RT_PITCH;      // [64][RED_PITCH]: red[kc*8+bl][jl]

    const int tid  = threadIdx.x;
    const int wid  = tid >> 5;          // warp id = K-chunk, also batch-lane in epilogue
    const int lane = tid & 31;          // lane = local j
    const int pb = blockIdx.x >> 5;
    const int pj = blockIdx.x & 31;
    const int b0 = pb*BPB, j0 = pj*JPB;
    const int kb = wid*128;

    // One-time: load + transpose W_res slice into SMEM (coalesced global reads,
    // conflict-free strided SMEM writes thanks to pitch 33).
    for (int jl = 0; jl < JPB; jl++) {
        const float* src = Wres + (size_t)(j0 + jl)*Rk;
        for (int k = tid; k < Rk; k += 256)
            Wt[k*WT_PITCH + jl] = src[k];
    }
    __syncthreads();

    for (int t = 0; t < Sk; t++) {
        // Prefetch pre for this thread's output (independent of the barrier).
        float preval = g_pre[((size_t)(b0 + wid)*Sk + t)*Rk + (j0 + lane)];

        // Grid barrier wait: all blocks must have published r_{t-1}.
        if (t > 0 && tid == 0) {
            unsigned target = (unsigned)NB * (unsigned)t;
            volatile unsigned* p = &g_bar;
            while (*p < target) { }
            __threadfence();            // acquire
        }
        __syncthreads();

        // Each warp loads its own 128-k x 8-b chunk of r_{t-1}, transposed.
        if (t > 0) {
#pragma unroll
            for (int kk = 0; kk < 4; kk++) {
                int kx = kb + kk*32 + lane;
#pragma unroll
                for (int bl = 0; bl < BPB; bl++) {
                    float v = g_rs[((size_t)(b0 + bl)*Sk + (t - 1))*Rk + kx];
                    rT[kx*RT_PITCH + bl] = v;
                }
            }
        } else {
#pragma unroll
            for (int kk = 0; kk < 4; kk++) {
                int kx = kb + kk*32 + lane;
#pragma unroll
                for (int bl = 0; bl < BPB; bl++)
                    rT[kx*RT_PITCH + bl] = 0.f;
            }
        }
        __syncwarp();

        // K-loop: 8 batch accumulators as 4 packed f32x2 pairs.
        unsigned long long a01 = 0ull, a23 = 0ull, a45 = 0ull, a67 = 0ull;
#pragma unroll 4
        for (int kk = 0; kk < 128; kk++) {
            int k = kb + kk;
            float w = Wt[k*WT_PITCH + lane];            // conflict-free LDS
            unsigned long long ww;
            asm("mov.b64 %0, {%1, %1};" : "=l"(ww) : "r"(__float_as_uint(w)));
            const ulonglong2* rp = reinterpret_cast<const ulonglong2*>(rT + k*RT_PITCH);
            ulonglong2 p0 = rp[0];                      // broadcast LDS.128
            ulonglong2 p1 = rp[1];
            asm("fma.rn.f32x2 %0, %1, %2, %0;" : "+l"(a01) : "l"(ww), "l"(p0.x));
            asm("fma.rn.f32x2 %0, %1, %2, %0;" : "+l"(a23) : "l"(ww), "l"(p0.y));
            asm("fma.rn.f32x2 %0, %1, %2, %0;" : "+l"(a45) : "l"(ww), "l"(p1.x));
            asm("fma.rn.f32x2 %0, %1, %2, %0;" : "+l"(a67) : "l"(ww), "l"(p1.y));
        }

        // Unpack and stage partials for the cross-warp K-reduction.
        {
            float a[8];
            unsigned lo, hi;
            asm("mov.b64 {%0,%1}, %2;" : "=r"(lo), "=r"(hi) : "l"(a01));
            a[0] = __uint_as_float(lo); a[1] = __uint_as_float(hi);
            asm("mov.b64 {%0,%1}, %2;" : "=r"(lo), "=r"(hi) : "l"(a23));
            a[2] = __uint_as_float(lo); a[3] = __uint_as_float(hi);
            asm("mov.b64 {%0,%1}, %2;" : "=r"(lo), "=r"(hi) : "l"(a45));
            a[4] = __uint_as_float(lo); a[5] = __uint_as_float(hi);
            asm("mov.b64 {%0,%1}, %2;" : "=r"(lo), "=r"(hi) : "l"(a67));
            a[6] = __uint_as_float(lo); a[7] = __uint_as_float(hi);
#pragma unroll
            for (int i = 0; i < 8; i++)
                red[(wid*8 + i)*RED_PITCH + lane] = a[i];
        }
        __syncthreads();

        // Epilogue: thread (wid,lane) finalizes output (b0+wid, j0+lane).
        {
            float s1 = preval;
#pragma unroll
            for (int kc = 0; kc < 8; kc++)
                s1 += red[(kc*8 + wid)*RED_PITCH + lane];
            // fast accurate tanh: sign-safe, overflow-safe
            float e  = __expf(2.f*fabsf(s1));
            float v  = 1.f - __fdividef(2.f, e + 1.f);
            float rv = copysignf(v, s1);
            g_rs[((size_t)(b0 + wid)*Sk + t)*Rk + (j0 + lane)] = rv;
        }
        __syncthreads();

        // Publish r_t.
        if (tid == 0 && t < Sk - 1) {
            __threadfence();            // release
            atomicAdd(&g_bar, 1u);
        }
    }
}

// ---------------------------------------------------------------------------
// Phase 3: out[row,o] = x[row,:] @ Wout[o,0:64] + rs[row,:] @ Wout[o,64:1088]
// Warp per row; HBM-bound on the 512 MB rs read (~100 us).
// ---------------------------------------------------------------------------
__global__ void __launch_bounds__(256) out_kernel(const float* __restrict__ x,
                                                  const float* __restrict__ Wout,
                                                  float* __restrict__ out)
{
    __shared__ float ws[Ok*1088];
    for (int idx = threadIdx.x; idx < Ok*1088; idx += 256) ws[idx] = Wout[idx];
    __syncthreads();

    int warp = threadIdx.x >> 5, lane = threadIdx.x & 31;
    for (size_t row = (size_t)blockIdx.x*8 + warp; row < (size_t)Bk*Sk;
         row += (size_t)gridDim.x*8) {
        const float* xr = x    + row*Ik;
        const float* rr = g_rs + row*Rk;
        float acc[8] = {0,0,0,0,0,0,0,0};
#pragma unroll
        for (int q = 0; q < 2; q++) {
            int k = q*32 + lane;
            float f = xr[k];
#pragma unroll
            for (int o = 0; o < 8; o++) acc[o] = fmaf(f, ws[o*1088 + k], acc[o]);
        }
#pragma unroll 4
        for (int q = 0; q < 32; q++) {
            int k = q*32 + lane;
            float f = rr[k];
#pragma unroll
            for (int o = 0; o < 8; o++) acc[o] = fmaf(f, ws[o*1088 + 64 + k], acc[o]);
        }
#pragma unroll
        for (int o = 0; o < 8; o++)
#pragma unroll
            for (int off = 16; off; off >>= 1)
                acc[o] += __shfl_xor_sync(0xffffffffu, acc[o], off);
        if (lane == 0) {
#pragma unroll
            for (int o = 0; o < 8; o++) out[row*Ok + o] = acc[o];
        }
    }
}

// ---------------------------------------------------------------------------
extern "C" void kernel_launch(void* const* d_in, const int* in_sizes, int n_in,
                              void* d_out, int out_size)
{
    (void)in_sizes; (void)n_in; (void)out_size;
    const float* x    = (const float*)d_in[0];
    const float* Win  = (const float*)d_in[1];
    const float* Wres = (const float*)d_in[2];
    const float* Wout = (const float*)d_in[3];
    float* out = (float*)d_out;

    cudaFuncSetAttribute(esn_main, cudaFuncAttributeMaxDynamicSharedMemorySize,
                         SMEM_BYTES);

    reset_kernel<<<1, 1>>>();
    pre_kernel<<<(Bk*Sk)/32, 256>>>(x, Win);
    esn_main<<<NB, 256, SMEM_BYTES>>>(Wres);
    out_kernel<<<2048, 256>>>(x, Wout, out);
}

// round 4
// speedup vs baseline: 1.3121x; 1.3121x over previous
#include <cuda_runtime.h>
#include <cstdint>
typedef unsigned long long ull;

#define Bk 32
#define Sk 4096
#define Ik 64
#define Rk 1024
#define Ok 8

#define NB 128
#define BPB 8        // batches per block
#define JPB 32       // j per block
#define RPB 80       // bytes per k-pair row in rP (8 batches x 8B + 16B pad)
#define STP 1026     // stage pitch (floats)
#define SMEM_BYTES (JPB*STP*4)   // 131328; also covers rP(40960)+red(8448)

__device__ float g_pre[(size_t)Bk*Sk*Rk];
__device__ float g_rs [(size_t)Bk*Sk*Rk];
__device__ float g_rbuf[2*Bk*Rk];
__device__ unsigned g_flags[NB*32];

__device__ __forceinline__ void fma2(ull& a, ull b, ull c) {
    asm("fma.rn.f32x2 %0, %1, %2, %0;" : "+l"(a) : "l"(b), "l"(c));
}
__device__ __forceinline__ float hsum2(ull a) {
    unsigned l, h; asm("mov.b64 {%0,%1}, %2;" : "=r"(l), "=r"(h) : "l"(a));
    return __uint_as_float(l) + __uint_as_float(h);
}

__global__ void reset_kernel() {
    if (threadIdx.x < NB) g_flags[threadIdx.x*32] = 0u;
}

// ---- Phase 1: pre = x @ W_in^T (f32x2 packed) ------------------------------
__global__ void __launch_bounds__(256) pre_kernel(const float* __restrict__ x,
                                                  const float* __restrict__ Win)
{
    __shared__ __align__(16) float xs[32*68];
    size_t rowBase = (size_t)blockIdx.x*32;
    for (int idx = threadIdx.x; idx < 32*64; idx += 256)
        xs[(idx>>6)*68 + (idx&63)] = x[(rowBase + (idx>>6))*64 + (idx&63)];
    __syncthreads();
    for (int jj = 0; jj < 4; jj++) {
        int j = jj*256 + threadIdx.x;
        ull w[32];
        const ull* wp = (const ull*)(Win + (size_t)j*64);
#pragma unroll
        for (int q = 0; q < 32; q++) w[q] = wp[q];
#pragma unroll 1
        for (int r = 0; r < 32; r++) {
            const ull* xr = (const ull*)&xs[r*68];
            ull a = 0, b = 0, c = 0, d = 0;
#pragma unroll
            for (int q = 0; q < 32; q += 4) {
                fma2(a, w[q], xr[q]);     fma2(b, w[q+1], xr[q+1]);
                fma2(c, w[q+2], xr[q+2]); fma2(d, w[q+3], xr[q+3]);
            }
            g_pre[(rowBase + r)*Rk + j] = (hsum2(a)+hsum2(b))+(hsum2(c)+hsum2(d));
        }
    }
}

// ---- Phase 2: persistent recurrence ----------------------------------------
__global__ void __launch_bounds__(256, 1) esn_main(const float* __restrict__ Wres)
{
    extern __shared__ __align__(16) float sm[];
    char* smc = (char*)sm;
    const int tid = threadIdx.x, wid = tid >> 5, lane = tid & 31;
    const int pb = blockIdx.x >> 5, pj = blockIdx.x & 31;
    const int b0 = pb*BPB, j0 = pj*JPB;
    const int kp0 = wid*64;                       // 64 k-pairs per warp

    // stage W slice, pull this thread's 64 (even,odd) weight pairs into regs
    for (int jl = 0; jl < JPB; jl++) {
        const float* src = Wres + (size_t)(j0 + jl)*Rk;
        for (int k = tid; k < Rk; k += 256) sm[jl*STP + k] = src[k];
    }
    __syncthreads();
    ull w2[64];
    {
        const ull* ws = (const ull*)(sm + lane*STP);
#pragma unroll
        for (int u = 0; u < 64; u++) w2[u] = ws[kp0 + u];
    }
    __syncthreads();

    char*  rP  = smc;                              // [512 kp][RPB]
    float* red = (float*)(smc + 512*RPB);          // [64][33]

    for (int t = 0; t < Sk; t++) {
        float preval = g_pre[((size_t)(b0 + wid)*Sk + t)*Rk + (j0 + lane)];

        if (t > 0) {   // wait for this warp's 4 producer blocks (same pb)
            const unsigned* fp = g_flags + (size_t)(pb*32 + (wid*4 + (lane & 3)))*32;
            unsigned v;
            do { asm volatile("ld.acquire.gpu.global.u32 %0, [%1];"
                              : "=r"(v) : "l"(fp) : "memory"); } while (v < (unsigned)t);
        }
        __syncwarp();

        if (t > 0) {   // stage r chunk as k-pairs: rP[kp] = 8 batches x (even,odd)
            const float2* src = (const float2*)(g_rbuf + (size_t)((t-1)&1)*(Bk*Rk));
#pragma unroll
            for (int kk = 0; kk < 2; kk++) {
                int kpx = kp0 + kk*32 + lane;
#pragma unroll
                for (int bl = 0; bl < BPB; bl++)
                    *(float2*)(rP + (size_t)kpx*RPB + bl*8) =
                        src[(size_t)(b0 + bl)*(Rk/2) + kpx];
            }
        } else {
            float2 z = make_float2(0.f, 0.f);
#pragma unroll
            for (int kk = 0; kk < 2; kk++) {
                int kpx = kp0 + kk*32 + lane;
#pragma unroll
                for (int bl = 0; bl < BPB; bl++)
                    *(float2*)(rP + (size_t)kpx*RPB + bl*8) = z;
            }
        }
        __syncwarp();

        ull a0=0,a1=0,a2=0,a3=0,a4=0,a5=0,a6=0,a7=0;
        const char* rb = rP + (size_t)kp0*RPB;
#pragma unroll
        for (int u = 0; u < 64; u++) {
            const ulonglong2* rp = (const ulonglong2*)(rb + u*RPB);
            ulonglong2 q0 = rp[0], q1 = rp[1], q2 = rp[2], q3 = rp[3];
            ull w = w2[u];
            fma2(a0, w, q0.x); fma2(a1, w, q0.y);
            fma2(a2, w, q1.x); fma2(a3, w, q1.y);
            fma2(a4, w, q2.x); fma2(a5, w, q2.y);
            fma2(a6, w, q3.x); fma2(a7, w, q3.y);
        }
        red[(wid*8+0)*33+lane] = hsum2(a0); red[(wid*8+1)*33+lane] = hsum2(a1);
        red[(wid*8+2)*33+lane] = hsum2(a2); red[(wid*8+3)*33+lane] = hsum2(a3);
        red[(wid*8+4)*33+lane] = hsum2(a4); red[(wid*8+5)*33+lane] = hsum2(a5);
        red[(wid*8+6)*33+lane] = hsum2(a6); red[(wid*8+7)*33+lane] = hsum2(a7);
        __syncthreads();

        {   // epilogue: thread (wid=batch-lane, lane=j)
            float s = preval;
#pragma unroll
            for (int kc = 0; kc < 8; kc++) s += red[(kc*8 + wid)*33 + lane];
            float e = __expf(2.f*fabsf(s));
            float rv = copysignf(1.f - __fdividef(2.f, e + 1.f), s);
            g_rs[((size_t)(b0 + wid)*Sk + t)*Rk + (j0 + lane)] = rv;
            if (t < Sk - 1)
                g_rbuf[(size_t)(t&1)*(Bk*Rk) + (size_t)(b0 + wid)*Rk + (j0 + lane)] = rv;
        }
        __syncthreads();

        if (tid == 0 && t < Sk - 1) {
            unsigned nv = (unsigned)(t + 1);
            asm volatile("st.release.gpu.global.u32 [%0], %1;"
                         :: "l"(g_flags + (size_t)blockIdx.x*32), "r"(nv) : "memory");
        }
    }
}

// ---- Phase 3: out = [x, rs] @ W_out^T --------------------------------------
__global__ void __launch_bounds__(256) out_kernel(const float* __restrict__ x,
                                                  const float* __restrict__ Wout,
                                                  float* __restrict__ out)
{
    __shared__ float ws[Ok*1088];
    for (int idx = threadIdx.x; idx < Ok*1088; idx += 256) ws[idx] = Wout[idx];
    __syncthreads();
    int warp = threadIdx.x >> 5, lane = threadIdx.x & 31;
    for (size_t row = (size_t)blockIdx.x*8 + warp; row < (size_t)Bk*Sk;
         row += (size_t)gridDim.x*8) {
        const float* xr = x + row*Ik;
        const float* rr = g_rs + row*Rk;
        float acc[8] = {0,0,0,0,0,0,0,0};
#pragma unroll
        for (int q = 0; q < 2; q++) {
            int k = q*32 + lane; float f = xr[k];
#pragma unroll
            for (int o = 0; o < 8; o++) acc[o] = fmaf(f, ws[o*1088 + k], acc[o]);
        }
#pragma unroll 4
        for (int q = 0; q < 32; q++) {
            int k = q*32 + lane; float f = rr[k];
#pragma unroll
            for (int o = 0; o < 8; o++) acc[o] = fmaf(f, ws[o*1088 + 64 + k], acc[o]);
        }
#pragma unroll
        for (int o = 0; o < 8; o++)
#pragma unroll
            for (int off = 16; off; off >>= 1)
                acc[o] += __shfl_xor_sync(0xffffffffu, acc[o], off);
        if (lane == 0)
#pragma unroll
            for (int o = 0; o < 8; o++) out[row*Ok + o] = acc[o];
    }
}

extern "C" void kernel_launch(void* const* d_in, const int* in_sizes, int n_in,
                              void* d_out, int out_size)
{
    (void)in_sizes; (void)n_in; (void)out_size;
    const float* x    = (const float*)d_in[0];
    const float* Win  = (const float*)d_in[1];
    const float* Wres = (const float*)d_in[2];
    const float* Wout = (const float*)d_in[3];
    cudaFuncSetAttribute(esn_main, cudaFuncAttributeMaxDynamicSharedMemorySize,
                         SMEM_BYTES);
    reset_kernel<<<1, 128>>>();
    pre_kernel<<<(Bk*Sk)/32, 256>>>(x, Win);
    esn_main<<<NB, 256, SMEM_BYTES>>>(Wres);
    out_kernel<<<2048, 256>>>(x, Wout, (float*)d_out);
}